// round 6
// baseline (speedup 1.0000x reference)
#include <cuda_runtime.h>
#include <cuda_fp16.h>

#define N_USERS 40000
#define N_ITEMS 20000
#define NNZ     1000000
#define D       64
#define N_TOTAL (N_USERS + N_ITEMS)
#define EPS     1e-8f
#define SCAN_BLOCKS 20
#define SCAN_CHUNK  1000

// ---------------- device scratch ----------------
__device__ uint4 g_lin_u[N_ITEMS * 8];
__device__ uint4 g_lin_i[N_USERS * 8];
__device__ uint4 g_emb_u0[N_USERS * 8];
__device__ uint4 g_emb_u1[N_USERS * 8];
__device__ uint4 g_emb_i0[N_ITEMS * 8];
__device__ uint4 g_emb_i1[N_ITEMS * 8];
__device__ float g_inv_u[N_USERS];
__device__ float g_inv_i[N_ITEMS];
__device__ float g_w_u[NNZ];        // per-edge unnormalized w, u-order
__device__ float g_w_i[NNZ];        // per-edge unnormalized w, i-order
__device__ int2  g_pk_u[NNZ];
__device__ int2  g_pk_i[NNZ];
__device__ int   g_i_src_u[NNZ];
__device__ int   g_u_ptr[N_USERS + 1];
__device__ int   g_i_ptr[N_ITEMS + 1];
__device__ int   g_i_cnt[N_ITEMS];
__device__ int   g_part[SCAN_BLOCKS];

// ---------------- helpers ----------------
__device__ __forceinline__ void acc8(float2& a0, float2& a1, float2& a2, float2& a3,
                                     uint4 v, float w) {
    float2 b;
    b = __half22float2(*(__half2*)&v.x); a0.x = fmaf(w, b.x, a0.x); a0.y = fmaf(w, b.y, a0.y);
    b = __half22float2(*(__half2*)&v.y); a1.x = fmaf(w, b.x, a1.x); a1.y = fmaf(w, b.y, a1.y);
    b = __half22float2(*(__half2*)&v.z); a2.x = fmaf(w, b.x, a2.x); a2.y = fmaf(w, b.y, a2.y);
    b = __half22float2(*(__half2*)&v.w); a3.x = fmaf(w, b.x, a3.x); a3.y = fmaf(w, b.y, a3.y);
}
__device__ __forceinline__ uint4 pack8(float2 a0, float2 a1, float2 a2, float2 a3) {
    uint4 r;
    *(__half2*)&r.x = __floats2half2_rn(a0.x, a0.y);
    *(__half2*)&r.y = __floats2half2_rn(a1.x, a1.y);
    *(__half2*)&r.z = __floats2half2_rn(a2.x, a2.y);
    *(__half2*)&r.w = __floats2half2_rn(a3.x, a3.y);
    return r;
}
__device__ __forceinline__ void xor_reduce_groups(float2& a0, float2& a1, float2& a2, float2& a3) {
    #pragma unroll
    for (int o = 8; o <= 16; o <<= 1) {
        a0.x += __shfl_xor_sync(0xffffffffu, a0.x, o);
        a0.y += __shfl_xor_sync(0xffffffffu, a0.y, o);
        a1.x += __shfl_xor_sync(0xffffffffu, a1.x, o);
        a1.y += __shfl_xor_sync(0xffffffffu, a1.y, o);
        a2.x += __shfl_xor_sync(0xffffffffu, a2.x, o);
        a2.y += __shfl_xor_sync(0xffffffffu, a2.y, o);
        a3.x += __shfl_xor_sync(0xffffffffu, a3.x, o);
        a3.y += __shfl_xor_sync(0xffffffffu, a3.y, o);
    }
}
__device__ __forceinline__ void store_out(float* __restrict__ out, int r, int c,
                                          float2 a0, float2 a1, float2 a2, float2 a3,
                                          float scale) {
    float4* o = (float4*)(out + (size_t)r * D + c * 8);
    float4 o0 = o[0], o1 = o[1];
    o0.x = (o0.x + a0.x) * scale; o0.y = (o0.y + a0.y) * scale;
    o0.z = (o0.z + a1.x) * scale; o0.w = (o0.w + a1.y) * scale;
    o1.x = (o1.x + a2.x) * scale; o1.y = (o1.y + a2.y) * scale;
    o1.z = (o1.z + a3.x) * scale; o1.w = (o1.w + a3.y) * scale;
    o[0] = o0; o[1] = o1;
}

// ---------------- K1: zero counts + user CSR ptr + fp16 conversion ----------------
__global__ void k_setup(const int* __restrict__ u_idx,
                        const float* __restrict__ user_linear,
                        const float* __restrict__ item_linear) {
    int t = blockIdx.x * blockDim.x + threadIdx.x;
    if (t < N_ITEMS) g_i_cnt[t] = 0;
    if (t <= N_USERS) {
        int lo = 0, hi = NNZ;
        while (lo < hi) { int mid = (lo + hi) >> 1; if (u_idx[mid] < t) lo = mid + 1; else hi = mid; }
        g_u_ptr[t] = lo;
    }
    const int NU = N_ITEMS * 8;
    const int NI = N_USERS * 8;
    if (t < NU) {
        const float4* s = (const float4*)user_linear;
        float4 x0 = s[2 * t], x1 = s[2 * t + 1];
        g_lin_u[t] = pack8(make_float2(x0.x, x0.y), make_float2(x0.z, x0.w),
                           make_float2(x1.x, x1.y), make_float2(x1.z, x1.w));
    } else if (t < NU + NI) {
        int k = t - NU;
        const float4* s = (const float4*)item_linear;
        float4 x0 = s[2 * k], x1 = s[2 * k + 1];
        g_lin_i[k] = pack8(make_float2(x0.x, x0.y), make_float2(x0.z, x0.w),
                           make_float2(x1.x, x1.y), make_float2(x1.z, x1.w));
    }
}

__global__ void k_count(const int* __restrict__ i_idx) {
    int e = blockIdx.x * blockDim.x + threadIdx.x;
    if (e < NNZ) atomicAdd(&g_i_cnt[i_idx[e]], 1);
}

__global__ void __launch_bounds__(256) k_part() {
    __shared__ int wsum[8];
    int b = blockIdx.x, tid = threadIdx.x;
    int s = 0;
    for (int k = tid; k < SCAN_CHUNK; k += 256) s += g_i_cnt[b * SCAN_CHUNK + k];
    #pragma unroll
    for (int o = 16; o; o >>= 1) s += __shfl_xor_sync(0xffffffffu, s, o);
    if ((tid & 31) == 0) wsum[tid >> 5] = s;
    __syncthreads();
    if (tid < 8) {
        int x = wsum[tid];
        #pragma unroll
        for (int o = 4; o; o >>= 1) x += __shfl_xor_sync(0xffu, x, o);
        if (tid == 0) g_part[b] = x;
    }
}

__global__ void __launch_bounds__(1024) k_blkscan() {
    __shared__ int wsum[32];
    __shared__ int base_s;
    int b = blockIdx.x, tid = threadIdx.x, lane = tid & 31, wid = tid >> 5;
    if (tid == 0) {
        int base = 0;
        #pragma unroll
        for (int k = 0; k < SCAN_BLOCKS; ++k) if (k < b) base += g_part[k];
        base_s = base;
    }
    int idx = b * SCAN_CHUNK + tid;
    int x = (tid < SCAN_CHUNK) ? g_i_cnt[idx] : 0;
    int t = x;
    #pragma unroll
    for (int o = 1; o < 32; o <<= 1) { int y = __shfl_up_sync(0xffffffffu, t, o); if (lane >= o) t += y; }
    if (lane == 31) wsum[wid] = t;
    __syncthreads();
    if (wid == 0) {
        int s = wsum[lane];
        #pragma unroll
        for (int o = 1; o < 32; o <<= 1) { int y = __shfl_up_sync(0xffffffffu, s, o); if (lane >= o) s += y; }
        wsum[lane] = s;
    }
    __syncthreads();
    int incl = t + (wid ? wsum[wid - 1] : 0);
    if (tid < SCAN_CHUNK) {
        g_i_ptr[idx] = base_s + incl - x;
        g_i_cnt[idx] = 0;
    }
    if (b == SCAN_BLOCKS - 1 && tid == 0) g_i_ptr[N_ITEMS] = NNZ;
}

__global__ void k_scatter(const int* __restrict__ u_idx, const int* __restrict__ i_idx) {
    int e = blockIdx.x * blockDim.x + threadIdx.x;
    if (e >= NNZ) return;
    int i = i_idx[e];
    int pos = g_i_ptr[i] + atomicAdd(&g_i_cnt[i], 1);
    g_i_src_u[pos] = u_idx[e];
}

// ---------------- base embeddings (warp per row) ----------------
__global__ void __launch_bounds__(256) k_emb(const int* __restrict__ i_idx,
                                             float* __restrict__ out) {
    int r = (blockIdx.x * blockDim.x + threadIdx.x) >> 5;
    if (r >= N_TOTAL) return;
    int lane = threadIdx.x & 31, g = lane >> 3, c = lane & 7;
    const uint4* __restrict__ src;
    const int* __restrict__ idxarr;
    int beg, end, row;
    if (r < N_USERS) {
        row = r; src = g_lin_u; idxarr = i_idx;
        beg = g_u_ptr[r]; end = g_u_ptr[r + 1];
    } else {
        row = r - N_USERS; src = g_lin_i; idxarr = g_i_src_u;
        beg = g_i_ptr[row]; end = g_i_ptr[row + 1];
    }
    float2 a0 = {0,0}, a1 = {0,0}, a2 = {0,0}, a3 = {0,0};
    for (int ch = beg; ch < end; ch += 4) {
        int e = ch + g;
        bool val = e < end;
        int idx = val ? idxarr[e] : 0;
        uint4 v = src[idx * 8 + c];
        acc8(a0, a1, a2, a3, v, val ? 1.0f : 0.0f);
    }
    xor_reduce_groups(a0, a1, a2, a3);
    float ss = a0.x*a0.x + a0.y*a0.y + a1.x*a1.x + a1.y*a1.y
             + a2.x*a2.x + a2.y*a2.y + a3.x*a3.x + a3.y*a3.y;
    #pragma unroll
    for (int o = 1; o <= 4; o <<= 1) ss += __shfl_xor_sync(0xffffffffu, ss, o);
    if (lane == 0) {
        float inv = 1.0f / fmaxf(sqrtf(ss), EPS);
        if (r < N_USERS) g_inv_u[row] = inv; else g_inv_i[row] = inv;
    }
    if (g == 0) {
        if (r < N_USERS) g_emb_u0[row * 8 + c] = pack8(a0, a1, a2, a3);
        else             g_emb_i0[row * 8 + c] = pack8(a0, a1, a2, a3);
        float4* o = (float4*)(out + (size_t)r * D + c * 8);
        o[0] = make_float4(a0.x, a0.y, a1.x, a1.y);
        o[1] = make_float4(a2.x, a2.y, a3.x, a3.y);
    }
}

// ---- FUSED: cosine weights + row-norm + layer-1 propagation + packing, both sides ----
// Single gather pass per edge: gathered neighbor row bv is used for BOTH the
// cosine dot product and the weighted accumulation; normalization is applied
// after the loop (it commutes through the linear sum).
__global__ void __launch_bounds__(256) k_wprop(const int* __restrict__ i_idx,
                                               float* __restrict__ out) {
    int r = (blockIdx.x * blockDim.x + threadIdx.x) >> 5;
    if (r >= N_TOTAL) return;
    int lane = threadIdx.x & 31, g = lane >> 3, c = lane & 7;
    const uint4* __restrict__ btab;
    const float* __restrict__ invb;
    const int* __restrict__ idxarr;
    float* __restrict__ warr;
    int2* __restrict__ pk;
    int beg, end, row;
    float inva;
    uint4 av;
    if (r < N_USERS) {
        row = r;
        av = g_emb_u0[row * 8 + c]; inva = g_inv_u[row];
        btab = g_emb_i0; invb = g_inv_i; idxarr = i_idx;
        warr = g_w_u; pk = g_pk_u;
        beg = g_u_ptr[row]; end = g_u_ptr[row + 1];
    } else {
        row = r - N_USERS;
        av = g_emb_i0[row * 8 + c]; inva = g_inv_i[row];
        btab = g_emb_u0; invb = g_inv_u; idxarr = g_i_src_u;
        warr = g_w_i; pk = g_pk_i;
        beg = g_i_ptr[row]; end = g_i_ptr[row + 1];
    }
    float2 A0 = __half22float2(*(__half2*)&av.x);
    float2 A1 = __half22float2(*(__half2*)&av.y);
    float2 A2 = __half22float2(*(__half2*)&av.z);
    float2 A3 = __half22float2(*(__half2*)&av.w);
    float2 a0 = {0,0}, a1 = {0,0}, a2 = {0,0}, a3 = {0,0};
    float sum = 0.f;
    for (int ch = beg; ch < end; ch += 4) {
        int e = ch + g;
        bool val = e < end;
        int idx = val ? idxarr[e] : 0;
        uint4 bv = btab[idx * 8 + c];
        float2 b;
        float d = 0.f;
        b = __half22float2(*(__half2*)&bv.x); d = fmaf(A0.x, b.x, d); d = fmaf(A0.y, b.y, d);
        b = __half22float2(*(__half2*)&bv.y); d = fmaf(A1.x, b.x, d); d = fmaf(A1.y, b.y, d);
        b = __half22float2(*(__half2*)&bv.z); d = fmaf(A2.x, b.x, d); d = fmaf(A2.y, b.y, d);
        b = __half22float2(*(__half2*)&bv.w); d = fmaf(A3.x, b.x, d); d = fmaf(A3.y, b.y, d);
        #pragma unroll
        for (int o = 1; o <= 4; o <<= 1) d += __shfl_xor_sync(0xffffffffu, d, o);
        // all 8 lanes of the group now hold the full dot product
        float w = val ? fmaf(d * inva * invb[idx], 0.5f, 0.5f) : 0.0f;
        acc8(a0, a1, a2, a3, bv, w);
        if (c == 0 && val) { warr[e] = w; sum += w; }
    }
    sum += __shfl_xor_sync(0xffffffffu, sum, 8);
    sum += __shfl_xor_sync(0xffffffffu, sum, 16);
    float invd = 1.0f / (sum + 1e-7f);
    invd = __shfl_sync(0xffffffffu, invd, 0);
    xor_reduce_groups(a0, a1, a2, a3);
    if (g == 0) {
        a0.x *= invd; a0.y *= invd; a1.x *= invd; a1.y *= invd;
        a2.x *= invd; a2.y *= invd; a3.x *= invd; a3.y *= invd;
        uint4 p = pack8(a0, a1, a2, a3);
        if (r < N_USERS) g_emb_u1[row * 8 + c] = p;
        else             g_emb_i1[row * 8 + c] = p;
        store_out(out, r, c, a0, a1, a2, a3, 1.0f);
    }
    __syncwarp();
    // pack normalized edge weights (sequential, cache-hot)
    for (int e = beg + lane; e < end; e += 32)
        pk[e] = make_int2(idxarr[e], __float_as_int(warr[e] * invd));
}

// ---------------- propagation layers 2,3 ----------------
__global__ void __launch_bounds__(256) k_prop(float* __restrict__ out, int flip,
                                              float scale, int write_dst) {
    int r = (blockIdx.x * blockDim.x + threadIdx.x) >> 5;
    if (r >= N_TOTAL) return;
    int lane = threadIdx.x & 31, g = lane >> 3, c = lane & 7;
    const int2* __restrict__ pk;
    const uint4* __restrict__ src;
    uint4* __restrict__ dst;
    int beg, end, row;
    if (r < N_USERS) {
        row = r; pk = g_pk_u;
        src = flip ? g_emb_i1 : g_emb_i0;
        dst = flip ? g_emb_u0 : g_emb_u1;
        beg = g_u_ptr[r]; end = g_u_ptr[r + 1];
    } else {
        row = r - N_USERS; pk = g_pk_i;
        src = flip ? g_emb_u1 : g_emb_u0;
        dst = flip ? g_emb_i0 : g_emb_i1;
        beg = g_i_ptr[row]; end = g_i_ptr[row + 1];
    }
    float2 a0 = {0,0}, a1 = {0,0}, a2 = {0,0}, a3 = {0,0};
    for (int ch = beg; ch < end; ch += 4) {
        int e = ch + g;
        int2 p = (e < end) ? pk[e] : make_int2(0, 0);
        uint4 v = src[p.x * 8 + c];
        acc8(a0, a1, a2, a3, v, __int_as_float(p.y));
    }
    xor_reduce_groups(a0, a1, a2, a3);
    if (g == 0) {
        if (write_dst) dst[row * 8 + c] = pack8(a0, a1, a2, a3);
        store_out(out, r, c, a0, a1, a2, a3, scale);
    }
}

// ---------------- launch ----------------
extern "C" void kernel_launch(void* const* d_in, const int* in_sizes, int n_in,
                              void* d_out, int out_size) {
    const float* user_linear = (const float*)d_in[0];
    const float* item_linear = (const float*)d_in[1];
    const int*   u_idx       = (const int*)d_in[2];
    const int*   i_idx       = (const int*)d_in[3];
    float* out = (float*)d_out;

    int setup_threads = (N_USERS + N_ITEMS) * 8;
    k_setup<<<(setup_threads + 255) / 256, 256>>>(u_idx, user_linear, item_linear);
    k_count<<<(NNZ + 255) / 256, 256>>>(i_idx);
    k_part<<<SCAN_BLOCKS, 256>>>();
    k_blkscan<<<SCAN_BLOCKS, 1024>>>();
    k_scatter<<<(NNZ + 255) / 256, 256>>>(u_idx, i_idx);

    k_emb<<<(N_TOTAL * 32 + 255) / 256, 256>>>(i_idx, out);
    // fused: weights + norm + layer-1 prop + packing (single gather pass, both sides)
    k_wprop<<<(N_TOTAL * 32 + 255) / 256, 256>>>(i_idx, out);

    // layers 2, 3 (layer 3 skips the dead ping-pong store)
    k_prop<<<(N_TOTAL * 32 + 255) / 256, 256>>>(out, 1, 1.0f, 1);
    k_prop<<<(N_TOTAL * 32 + 255) / 256, 256>>>(out, 0, 0.25f, 0);
}

// round 7
// speedup vs baseline: 1.0609x; 1.0609x over previous
#include <cuda_runtime.h>
#include <cuda_fp16.h>

#define N_USERS 40000
#define N_ITEMS 20000
#define NNZ     1000000
#define D       64
#define N_TOTAL (N_USERS + N_ITEMS)
#define EPS     1e-8f
#define NB_COUNT ((NNZ + 255) / 256)
#define NB_EMBU  ((N_USERS * 32 + 255) / 256)

// ---------------- device scratch ----------------
__device__ uint4 g_lin_u[N_ITEMS * 8];
__device__ uint4 g_lin_i[N_USERS * 8];
__device__ uint4 g_emb_u0[N_USERS * 8];
__device__ uint4 g_emb_u1[N_USERS * 8];
__device__ uint4 g_emb_i0[N_ITEMS * 8];
__device__ uint4 g_emb_i1[N_ITEMS * 8];
__device__ float g_inv_u[N_USERS];
__device__ float g_inv_i[N_ITEMS];
__device__ float g_w_u[NNZ];
__device__ float g_w_i[NNZ];
__device__ int2  g_pk_u[NNZ];
__device__ int2  g_pk_i[NNZ];
__device__ int   g_i_src_u[NNZ];
__device__ int   g_slot[NNZ];
__device__ int   g_u_ptr[N_USERS + 1];
__device__ int   g_i_ptr[N_ITEMS + 1];
__device__ int   g_i_cnt[N_ITEMS];

// ---------------- helpers ----------------
__device__ __forceinline__ void acc8(float2& a0, float2& a1, float2& a2, float2& a3,
                                     uint4 v, float w) {
    float2 b;
    b = __half22float2(*(__half2*)&v.x); a0.x = fmaf(w, b.x, a0.x); a0.y = fmaf(w, b.y, a0.y);
    b = __half22float2(*(__half2*)&v.y); a1.x = fmaf(w, b.x, a1.x); a1.y = fmaf(w, b.y, a1.y);
    b = __half22float2(*(__half2*)&v.z); a2.x = fmaf(w, b.x, a2.x); a2.y = fmaf(w, b.y, a2.y);
    b = __half22float2(*(__half2*)&v.w); a3.x = fmaf(w, b.x, a3.x); a3.y = fmaf(w, b.y, a3.y);
}
__device__ __forceinline__ uint4 pack8(float2 a0, float2 a1, float2 a2, float2 a3) {
    uint4 r;
    *(__half2*)&r.x = __floats2half2_rn(a0.x, a0.y);
    *(__half2*)&r.y = __floats2half2_rn(a1.x, a1.y);
    *(__half2*)&r.z = __floats2half2_rn(a2.x, a2.y);
    *(__half2*)&r.w = __floats2half2_rn(a3.x, a3.y);
    return r;
}
__device__ __forceinline__ void xor_reduce_groups(float2& a0, float2& a1, float2& a2, float2& a3) {
    #pragma unroll
    for (int o = 8; o <= 16; o <<= 1) {
        a0.x += __shfl_xor_sync(0xffffffffu, a0.x, o);
        a0.y += __shfl_xor_sync(0xffffffffu, a0.y, o);
        a1.x += __shfl_xor_sync(0xffffffffu, a1.x, o);
        a1.y += __shfl_xor_sync(0xffffffffu, a1.y, o);
        a2.x += __shfl_xor_sync(0xffffffffu, a2.x, o);
        a2.y += __shfl_xor_sync(0xffffffffu, a2.y, o);
        a3.x += __shfl_xor_sync(0xffffffffu, a3.x, o);
        a3.y += __shfl_xor_sync(0xffffffffu, a3.y, o);
    }
}
__device__ __forceinline__ void store_out(float* __restrict__ out, int r, int c,
                                          float2 a0, float2 a1, float2 a2, float2 a3,
                                          float scale) {
    float4* o = (float4*)(out + (size_t)r * D + c * 8);
    float4 o0 = o[0], o1 = o[1];
    o0.x = (o0.x + a0.x) * scale; o0.y = (o0.y + a0.y) * scale;
    o0.z = (o0.z + a1.x) * scale; o0.w = (o0.w + a1.y) * scale;
    o1.x = (o1.x + a2.x) * scale; o1.y = (o1.y + a2.y) * scale;
    o1.z = (o1.z + a3.x) * scale; o1.w = (o1.w + a3.y) * scale;
    o[0] = o0; o[1] = o1;
}

// ---------------- K1: zero counts + user CSR ptr + fp16 conversion ----------------
__global__ void k_setup(const int* __restrict__ u_idx,
                        const float* __restrict__ user_linear,
                        const float* __restrict__ item_linear) {
    int t = blockIdx.x * blockDim.x + threadIdx.x;
    if (t < N_ITEMS) g_i_cnt[t] = 0;
    if (t <= N_USERS) {
        int lo = 0, hi = NNZ;
        while (lo < hi) { int mid = (lo + hi) >> 1; if (u_idx[mid] < t) lo = mid + 1; else hi = mid; }
        g_u_ptr[t] = lo;
    }
    const int NU = N_ITEMS * 8;
    const int NI = N_USERS * 8;
    if (t < NU) {
        const float4* s = (const float4*)user_linear;
        float4 x0 = s[2 * t], x1 = s[2 * t + 1];
        g_lin_u[t] = pack8(make_float2(x0.x, x0.y), make_float2(x0.z, x0.w),
                           make_float2(x1.x, x1.y), make_float2(x1.z, x1.w));
    } else if (t < NU + NI) {
        int k = t - NU;
        const float4* s = (const float4*)item_linear;
        float4 x0 = s[2 * k], x1 = s[2 * k + 1];
        g_lin_i[k] = pack8(make_float2(x0.x, x0.y), make_float2(x0.z, x0.w),
                           make_float2(x1.x, x1.y), make_float2(x1.z, x1.w));
    }
}

// ---------------- K2: fused item-degree count + user-side base embeddings ----------------
__global__ void __launch_bounds__(256) k_count_embu(const int* __restrict__ i_idx,
                                                    float* __restrict__ out) {
    if (blockIdx.x < NB_COUNT) {
        int e = blockIdx.x * 256 + threadIdx.x;
        if (e < NNZ) atomicAdd(&g_i_cnt[i_idx[e]], 1);
        return;
    }
    int r = ((blockIdx.x - NB_COUNT) * 256 + threadIdx.x) >> 5;
    if (r >= N_USERS) return;
    int lane = threadIdx.x & 31, g = lane >> 3, c = lane & 7;
    int beg = g_u_ptr[r], end = g_u_ptr[r + 1];
    float2 a0 = {0,0}, a1 = {0,0}, a2 = {0,0}, a3 = {0,0};
    for (int ch = beg; ch < end; ch += 4) {
        int e = ch + g;
        bool val = e < end;
        int idx = val ? i_idx[e] : 0;
        uint4 v = g_lin_u[idx * 8 + c];
        acc8(a0, a1, a2, a3, v, val ? 1.0f : 0.0f);
    }
    xor_reduce_groups(a0, a1, a2, a3);
    float ss = a0.x*a0.x + a0.y*a0.y + a1.x*a1.x + a1.y*a1.y
             + a2.x*a2.x + a2.y*a2.y + a3.x*a3.x + a3.y*a3.y;
    #pragma unroll
    for (int o = 1; o <= 4; o <<= 1) ss += __shfl_xor_sync(0xffffffffu, ss, o);
    if (lane == 0) g_inv_u[r] = 1.0f / fmaxf(sqrtf(ss), EPS);
    if (g == 0) {
        g_emb_u0[r * 8 + c] = pack8(a0, a1, a2, a3);
        float4* o = (float4*)(out + (size_t)r * D + c * 8);
        o[0] = make_float4(a0.x, a0.y, a1.x, a1.y);
        o[1] = make_float4(a2.x, a2.y, a3.x, a3.y);
    }
}

// ---------------- K3: single-block vectorized exclusive scan ----------------
__global__ void __launch_bounds__(1024) k_scan1() {
    // 20000 ints = 5000 int4; thread t (t<1000) owns int4 [t*5, t*5+5)
    __shared__ int wsum[32];
    int tid = threadIdx.x, lane = tid & 31, wid = tid >> 5;
    const int4* cnt4 = (const int4*)g_i_cnt;
    int4* ptr4 = (int4*)g_i_ptr;         // N_ITEMS multiple of 4 -> aligned writes
    int4* cz4 = (int4*)g_i_cnt;
    int v[20];
    int s = 0;
    if (tid < 1000) {
        #pragma unroll
        for (int k = 0; k < 5; ++k) {
            int4 x = cnt4[tid * 5 + k];
            v[4*k+0] = s; s += x.x;
            v[4*k+1] = s; s += x.y;
            v[4*k+2] = s; s += x.z;
            v[4*k+3] = s; s += x.w;
        }
    }
    int t = s;
    #pragma unroll
    for (int o = 1; o < 32; o <<= 1) { int y = __shfl_up_sync(0xffffffffu, t, o); if (lane >= o) t += y; }
    if (lane == 31) wsum[wid] = t;
    __syncthreads();
    if (wid == 0) {
        int x = wsum[lane];
        #pragma unroll
        for (int o = 1; o < 32; o <<= 1) { int y = __shfl_up_sync(0xffffffffu, x, o); if (lane >= o) x += y; }
        wsum[lane] = x;
    }
    __syncthreads();
    int offset = (t - s) + (wid ? wsum[wid - 1] : 0);
    if (tid < 1000) {
        #pragma unroll
        for (int k = 0; k < 5; ++k) {
            ptr4[tid * 5 + k] = make_int4(offset + v[4*k], offset + v[4*k+1],
                                          offset + v[4*k+2], offset + v[4*k+3]);
            cz4[tid * 5 + k] = make_int4(0, 0, 0, 0);
        }
    }
    if (tid == 0) g_i_ptr[N_ITEMS] = NNZ;
}

__global__ void k_scatter(const int* __restrict__ u_idx, const int* __restrict__ i_idx) {
    int e = blockIdx.x * blockDim.x + threadIdx.x;
    if (e >= NNZ) return;
    int i = i_idx[e];
    int pos = g_i_ptr[i] + atomicAdd(&g_i_cnt[i], 1);
    g_i_src_u[pos] = u_idx[e];
    g_slot[e] = pos;
}

// ---------------- item-side base embeddings ----------------
__global__ void __launch_bounds__(256) k_emb_i(float* __restrict__ out) {
    int r = (blockIdx.x * blockDim.x + threadIdx.x) >> 5;
    if (r >= N_ITEMS) return;
    int lane = threadIdx.x & 31, g = lane >> 3, c = lane & 7;
    int beg = g_i_ptr[r], end = g_i_ptr[r + 1];
    float2 a0 = {0,0}, a1 = {0,0}, a2 = {0,0}, a3 = {0,0};
    for (int ch = beg; ch < end; ch += 4) {
        int p = ch + g;
        bool val = p < end;
        int idx = val ? g_i_src_u[p] : 0;
        uint4 v = g_lin_i[idx * 8 + c];
        acc8(a0, a1, a2, a3, v, val ? 1.0f : 0.0f);
    }
    xor_reduce_groups(a0, a1, a2, a3);
    float ss = a0.x*a0.x + a0.y*a0.y + a1.x*a1.x + a1.y*a1.y
             + a2.x*a2.x + a2.y*a2.y + a3.x*a3.x + a3.y*a3.y;
    #pragma unroll
    for (int o = 1; o <= 4; o <<= 1) ss += __shfl_xor_sync(0xffffffffu, ss, o);
    if (lane == 0) g_inv_i[r] = 1.0f / fmaxf(sqrtf(ss), EPS);
    if (g == 0) {
        g_emb_i0[r * 8 + c] = pack8(a0, a1, a2, a3);
        float4* o = (float4*)(out + (size_t)(N_USERS + r) * D + c * 8);
        o[0] = make_float4(a0.x, a0.y, a1.x, a1.y);
        o[1] = make_float4(a2.x, a2.y, a3.x, a3.y);
    }
}

// ---- weights + u-norm + FUSED layer-1 user propagation + pk_u packing (warp per user) ----
__global__ void __launch_bounds__(256) k_weights(const int* __restrict__ i_idx,
                                                 float* __restrict__ out) {
    int u = (blockIdx.x * blockDim.x + threadIdx.x) >> 5;
    if (u >= N_USERS) return;
    int lane = threadIdx.x & 31, g = lane >> 3, c = lane & 7;
    int beg = g_u_ptr[u], end = g_u_ptr[u + 1];
    uint4 av = g_emb_u0[u * 8 + c];
    float2 A0 = __half22float2(*(__half2*)&av.x);
    float2 A1 = __half22float2(*(__half2*)&av.y);
    float2 A2 = __half22float2(*(__half2*)&av.z);
    float2 A3 = __half22float2(*(__half2*)&av.w);
    float invu = g_inv_u[u];
    float sum = 0.f;
    // pass 1: cosine weights
    for (int ch = beg; ch < end; ch += 4) {
        int e = ch + g;
        bool val = e < end;
        int i = val ? i_idx[e] : 0;
        uint4 bv = g_emb_i0[i * 8 + c];
        float2 b;
        float d = 0.f;
        b = __half22float2(*(__half2*)&bv.x); d = fmaf(A0.x, b.x, d); d = fmaf(A0.y, b.y, d);
        b = __half22float2(*(__half2*)&bv.y); d = fmaf(A1.x, b.x, d); d = fmaf(A1.y, b.y, d);
        b = __half22float2(*(__half2*)&bv.z); d = fmaf(A2.x, b.x, d); d = fmaf(A2.y, b.y, d);
        b = __half22float2(*(__half2*)&bv.w); d = fmaf(A3.x, b.x, d); d = fmaf(A3.y, b.y, d);
        #pragma unroll
        for (int o = 1; o <= 4; o <<= 1) d += __shfl_xor_sync(0xffffffffu, d, o);
        if (c == 0 && val) {
            float s = d * invu * g_inv_i[i];
            float w = fmaf(s, 0.5f, 0.5f);
            g_w_u[e] = w; g_w_i[g_slot[e]] = w; sum += w;
        }
    }
    sum += __shfl_xor_sync(0xffffffffu, sum, 8);
    sum += __shfl_xor_sync(0xffffffffu, sum, 16);
    float invd = 1.0f / (sum + 1e-7f);
    invd = __shfl_sync(0xffffffffu, invd, 0);
    __syncwarp();
    __threadfence_block();
    // pass 2: layer-1 user propagation over the same (cache-warm) item rows + pk_u packing
    float2 a0 = {0,0}, a1 = {0,0}, a2 = {0,0}, a3 = {0,0};
    for (int ch = beg; ch < end; ch += 4) {
        int e = ch + g;
        bool val = e < end;
        int i = val ? i_idx[e] : 0;
        float wn = val ? g_w_u[e] * invd : 0.0f;
        if (c == 0 && val) g_pk_u[e] = make_int2(i, __float_as_int(wn));
        uint4 v = g_emb_i0[i * 8 + c];
        acc8(a0, a1, a2, a3, v, wn);
    }
    xor_reduce_groups(a0, a1, a2, a3);
    if (g == 0) {
        g_emb_u1[u * 8 + c] = pack8(a0, a1, a2, a3);
        store_out(out, u, c, a0, a1, a2, a3, 1.0f);
    }
}

// ---- i-norm + FUSED layer-1 item propagation + pk_i packing (warp per item) ----
__global__ void __launch_bounds__(256) k_norm_i(float* __restrict__ out) {
    int i = (blockIdx.x * blockDim.x + threadIdx.x) >> 5;
    if (i >= N_ITEMS) return;
    int lane = threadIdx.x & 31, g = lane >> 3, c = lane & 7;
    int beg = g_i_ptr[i], end = g_i_ptr[i + 1];
    float s = 0.f;
    for (int p = beg + lane; p < end; p += 32) s += g_w_i[p];
    #pragma unroll
    for (int o = 16; o; o >>= 1) s += __shfl_xor_sync(0xffffffffu, s, o);
    float invd = 1.0f / (s + 1e-7f);
    float2 a0 = {0,0}, a1 = {0,0}, a2 = {0,0}, a3 = {0,0};
    for (int ch = beg; ch < end; ch += 4) {
        int p = ch + g;
        bool val = p < end;
        int uu = val ? g_i_src_u[p] : 0;
        float wn = val ? g_w_i[p] * invd : 0.0f;
        if (c == 0 && val) g_pk_i[p] = make_int2(uu, __float_as_int(wn));
        uint4 v = g_emb_u0[uu * 8 + c];
        acc8(a0, a1, a2, a3, v, wn);
    }
    xor_reduce_groups(a0, a1, a2, a3);
    if (g == 0) {
        g_emb_i1[i * 8 + c] = pack8(a0, a1, a2, a3);
        store_out(out, N_USERS + i, c, a0, a1, a2, a3, 1.0f);
    }
}

// ---------------- propagation layers 2,3 ----------------
__global__ void __launch_bounds__(256) k_prop(float* __restrict__ out, int flip,
                                              float scale, int write_dst) {
    int r = (blockIdx.x * blockDim.x + threadIdx.x) >> 5;
    if (r >= N_TOTAL) return;
    int lane = threadIdx.x & 31, g = lane >> 3, c = lane & 7;
    const int2* __restrict__ pk;
    const uint4* __restrict__ src;
    uint4* __restrict__ dst;
    int beg, end, row;
    if (r < N_USERS) {
        row = r; pk = g_pk_u;
        src = flip ? g_emb_i1 : g_emb_i0;
        dst = flip ? g_emb_u0 : g_emb_u1;
        beg = g_u_ptr[r]; end = g_u_ptr[r + 1];
    } else {
        row = r - N_USERS; pk = g_pk_i;
        src = flip ? g_emb_u1 : g_emb_u0;
        dst = flip ? g_emb_i0 : g_emb_i1;
        beg = g_i_ptr[row]; end = g_i_ptr[row + 1];
    }
    float2 a0 = {0,0}, a1 = {0,0}, a2 = {0,0}, a3 = {0,0};
    for (int ch = beg; ch < end; ch += 4) {
        int e = ch + g;
        int2 p = (e < end) ? pk[e] : make_int2(0, 0);
        uint4 v = src[p.x * 8 + c];
        acc8(a0, a1, a2, a3, v, __int_as_float(p.y));
    }
    xor_reduce_groups(a0, a1, a2, a3);
    if (g == 0) {
        if (write_dst) dst[row * 8 + c] = pack8(a0, a1, a2, a3);
        store_out(out, r, c, a0, a1, a2, a3, scale);
    }
}

// ---------------- launch ----------------
extern "C" void kernel_launch(void* const* d_in, const int* in_sizes, int n_in,
                              void* d_out, int out_size) {
    const float* user_linear = (const float*)d_in[0];
    const float* item_linear = (const float*)d_in[1];
    const int*   u_idx       = (const int*)d_in[2];
    const int*   i_idx       = (const int*)d_in[3];
    float* out = (float*)d_out;

    int setup_threads = (N_USERS + N_ITEMS) * 8;
    k_setup<<<(setup_threads + 255) / 256, 256>>>(u_idx, user_linear, item_linear);
    // fused: item-degree counting + user-side base embeddings (independent halves)
    k_count_embu<<<NB_COUNT + NB_EMBU, 256>>>(i_idx, out);
    k_scan1<<<1, 1024>>>();
    k_scatter<<<(NNZ + 255) / 256, 256>>>(u_idx, i_idx);
    k_emb_i<<<(N_ITEMS * 32 + 255) / 256, 256>>>(out);

    // weights + u-norm + layer-1 user prop; then i-norm + layer-1 item prop
    k_weights<<<(N_USERS * 32 + 255) / 256, 256>>>(i_idx, out);
    k_norm_i<<<(N_ITEMS * 32 + 255) / 256, 256>>>(out);

    // layers 2, 3 (layer 3 skips the dead ping-pong store)
    k_prop<<<(N_TOTAL * 32 + 255) / 256, 256>>>(out, 1, 1.0f, 1);
    k_prop<<<(N_TOTAL * 32 + 255) / 256, 256>>>(out, 0, 0.25f, 0);
}

// round 8
// speedup vs baseline: 1.1223x; 1.0579x over previous
#include <cuda_runtime.h>
#include <cuda_fp16.h>

#define N_USERS 40000
#define N_ITEMS 20000
#define NNZ     1000000
#define D       64
#define N_TOTAL (N_USERS + N_ITEMS)
#define EPS     1e-8f
#define NB_COUNT ((NNZ + 255) / 256)
#define NB_EMBU  ((N_USERS * 32 + 255) / 256)

// ---------------- device scratch ----------------
__device__ uint4 g_lin_u[N_ITEMS * 8];
__device__ uint4 g_lin_i[N_USERS * 8];
__device__ uint4 g_emb_u0[N_USERS * 8];
__device__ uint4 g_emb_u1[N_USERS * 8];
__device__ uint4 g_emb_i0[N_ITEMS * 8];
__device__ uint4 g_emb_i1[N_ITEMS * 8];
__device__ float g_inv_u[N_USERS];
__device__ float g_inv_i[N_ITEMS];
__device__ float g_w_u[NNZ];
__device__ float g_w_i[NNZ];
__device__ int2  g_pk_u[NNZ];
__device__ int2  g_pk_i[NNZ];
__device__ int   g_i_src_u[NNZ];
__device__ int   g_slot[NNZ];     // phase 1: rank within item segment; phase 2: final slot
__device__ int   g_u_ptr[N_USERS + 1];
__device__ int   g_i_ptr[N_ITEMS + 1];
__device__ int   g_i_cnt[N_ITEMS];

// ---------------- helpers ----------------
__device__ __forceinline__ void acc8(float2& a0, float2& a1, float2& a2, float2& a3,
                                     uint4 v, float w) {
    float2 b;
    b = __half22float2(*(__half2*)&v.x); a0.x = fmaf(w, b.x, a0.x); a0.y = fmaf(w, b.y, a0.y);
    b = __half22float2(*(__half2*)&v.y); a1.x = fmaf(w, b.x, a1.x); a1.y = fmaf(w, b.y, a1.y);
    b = __half22float2(*(__half2*)&v.z); a2.x = fmaf(w, b.x, a2.x); a2.y = fmaf(w, b.y, a2.y);
    b = __half22float2(*(__half2*)&v.w); a3.x = fmaf(w, b.x, a3.x); a3.y = fmaf(w, b.y, a3.y);
}
__device__ __forceinline__ uint4 pack8(float2 a0, float2 a1, float2 a2, float2 a3) {
    uint4 r;
    *(__half2*)&r.x = __floats2half2_rn(a0.x, a0.y);
    *(__half2*)&r.y = __floats2half2_rn(a1.x, a1.y);
    *(__half2*)&r.z = __floats2half2_rn(a2.x, a2.y);
    *(__half2*)&r.w = __floats2half2_rn(a3.x, a3.y);
    return r;
}
__device__ __forceinline__ void xor_reduce_groups(float2& a0, float2& a1, float2& a2, float2& a3) {
    #pragma unroll
    for (int o = 8; o <= 16; o <<= 1) {
        a0.x += __shfl_xor_sync(0xffffffffu, a0.x, o);
        a0.y += __shfl_xor_sync(0xffffffffu, a0.y, o);
        a1.x += __shfl_xor_sync(0xffffffffu, a1.x, o);
        a1.y += __shfl_xor_sync(0xffffffffu, a1.y, o);
        a2.x += __shfl_xor_sync(0xffffffffu, a2.x, o);
        a2.y += __shfl_xor_sync(0xffffffffu, a2.y, o);
        a3.x += __shfl_xor_sync(0xffffffffu, a3.x, o);
        a3.y += __shfl_xor_sync(0xffffffffu, a3.y, o);
    }
}
__device__ __forceinline__ void store_out(float* __restrict__ out, int r, int c,
                                          float2 a0, float2 a1, float2 a2, float2 a3,
                                          float scale) {
    float4* o = (float4*)(out + (size_t)r * D + c * 8);
    float4 o0 = o[0], o1 = o[1];
    o0.x = (o0.x + a0.x) * scale; o0.y = (o0.y + a0.y) * scale;
    o0.z = (o0.z + a1.x) * scale; o0.w = (o0.w + a1.y) * scale;
    o1.x = (o1.x + a2.x) * scale; o1.y = (o1.y + a2.y) * scale;
    o1.z = (o1.z + a3.x) * scale; o1.w = (o1.w + a3.y) * scale;
    o[0] = o0; o[1] = o1;
}

// ---------------- K1: zero counts + user CSR ptr + fp16 conversion ----------------
__global__ void k_setup(const int* __restrict__ u_idx,
                        const float* __restrict__ user_linear,
                        const float* __restrict__ item_linear) {
    int t = blockIdx.x * blockDim.x + threadIdx.x;
    if (t < N_ITEMS) g_i_cnt[t] = 0;
    if (t <= N_USERS) {
        int lo = 0, hi = NNZ;
        while (lo < hi) { int mid = (lo + hi) >> 1; if (u_idx[mid] < t) lo = mid + 1; else hi = mid; }
        g_u_ptr[t] = lo;
    }
    const int NU = N_ITEMS * 8;
    const int NI = N_USERS * 8;
    if (t < NU) {
        const float4* s = (const float4*)user_linear;
        float4 x0 = s[2 * t], x1 = s[2 * t + 1];
        g_lin_u[t] = pack8(make_float2(x0.x, x0.y), make_float2(x0.z, x0.w),
                           make_float2(x1.x, x1.y), make_float2(x1.z, x1.w));
    } else if (t < NU + NI) {
        int k = t - NU;
        const float4* s = (const float4*)item_linear;
        float4 x0 = s[2 * k], x1 = s[2 * k + 1];
        g_lin_i[k] = pack8(make_float2(x0.x, x0.y), make_float2(x0.z, x0.w),
                           make_float2(x1.x, x1.y), make_float2(x1.z, x1.w));
    }
}

// ---- K2: fused item-degree count (capturing ranks) + user-side base embeddings ----
__global__ void __launch_bounds__(256) k_count_embu(const int* __restrict__ i_idx,
                                                    float* __restrict__ out) {
    if (blockIdx.x < NB_COUNT) {
        int e = blockIdx.x * 256 + threadIdx.x;
        if (e < NNZ) g_slot[e] = atomicAdd(&g_i_cnt[i_idx[e]], 1);  // rank in segment
        return;
    }
    int r = ((blockIdx.x - NB_COUNT) * 256 + threadIdx.x) >> 5;
    if (r >= N_USERS) return;
    int lane = threadIdx.x & 31, g = lane >> 3, c = lane & 7;
    int beg = g_u_ptr[r], end = g_u_ptr[r + 1];
    float2 a0 = {0,0}, a1 = {0,0}, a2 = {0,0}, a3 = {0,0};
    for (int ch = beg; ch < end; ch += 4) {
        int e = ch + g;
        bool val = e < end;
        int idx = val ? i_idx[e] : 0;
        uint4 v = g_lin_u[idx * 8 + c];
        acc8(a0, a1, a2, a3, v, val ? 1.0f : 0.0f);
    }
    xor_reduce_groups(a0, a1, a2, a3);
    float ss = a0.x*a0.x + a0.y*a0.y + a1.x*a1.x + a1.y*a1.y
             + a2.x*a2.x + a2.y*a2.y + a3.x*a3.x + a3.y*a3.y;
    #pragma unroll
    for (int o = 1; o <= 4; o <<= 1) ss += __shfl_xor_sync(0xffffffffu, ss, o);
    if (lane == 0) g_inv_u[r] = 1.0f / fmaxf(sqrtf(ss), EPS);
    if (g == 0) {
        g_emb_u0[r * 8 + c] = pack8(a0, a1, a2, a3);
        float4* o = (float4*)(out + (size_t)r * D + c * 8);
        o[0] = make_float4(a0.x, a0.y, a1.x, a1.y);
        o[1] = make_float4(a2.x, a2.y, a3.x, a3.y);
    }
}

// ---------------- K3: single-block vectorized exclusive scan ----------------
__global__ void __launch_bounds__(1024) k_scan1() {
    __shared__ int wsum[32];
    int tid = threadIdx.x, lane = tid & 31, wid = tid >> 5;
    const int4* cnt4 = (const int4*)g_i_cnt;
    int4* ptr4 = (int4*)g_i_ptr;
    int v[20];
    int s = 0;
    if (tid < 1000) {
        #pragma unroll
        for (int k = 0; k < 5; ++k) {
            int4 x = cnt4[tid * 5 + k];
            v[4*k+0] = s; s += x.x;
            v[4*k+1] = s; s += x.y;
            v[4*k+2] = s; s += x.z;
            v[4*k+3] = s; s += x.w;
        }
    }
    int t = s;
    #pragma unroll
    for (int o = 1; o < 32; o <<= 1) { int y = __shfl_up_sync(0xffffffffu, t, o); if (lane >= o) t += y; }
    if (lane == 31) wsum[wid] = t;
    __syncthreads();
    if (wid == 0) {
        int x = wsum[lane];
        #pragma unroll
        for (int o = 1; o < 32; o <<= 1) { int y = __shfl_up_sync(0xffffffffu, x, o); if (lane >= o) x += y; }
        wsum[lane] = x;
    }
    __syncthreads();
    int offset = (t - s) + (wid ? wsum[wid - 1] : 0);
    if (tid < 1000) {
        #pragma unroll
        for (int k = 0; k < 5; ++k) {
            ptr4[tid * 5 + k] = make_int4(offset + v[4*k], offset + v[4*k+1],
                                          offset + v[4*k+2], offset + v[4*k+3]);
        }
    }
    if (tid == 0) g_i_ptr[N_ITEMS] = NNZ;
}

// ---------------- K4: atomic-free scatter using precomputed ranks ----------------
__global__ void k_scatter(const int* __restrict__ u_idx, const int* __restrict__ i_idx) {
    int e = blockIdx.x * blockDim.x + threadIdx.x;
    if (e >= NNZ) return;
    int i = i_idx[e];
    int pos = g_i_ptr[i] + g_slot[e];
    g_i_src_u[pos] = u_idx[e];
    g_slot[e] = pos;
}

// ---------------- item-side base embeddings ----------------
__global__ void __launch_bounds__(256) k_emb_i(float* __restrict__ out) {
    int r = (blockIdx.x * blockDim.x + threadIdx.x) >> 5;
    if (r >= N_ITEMS) return;
    int lane = threadIdx.x & 31, g = lane >> 3, c = lane & 7;
    int beg = g_i_ptr[r], end = g_i_ptr[r + 1];
    float2 a0 = {0,0}, a1 = {0,0}, a2 = {0,0}, a3 = {0,0};
    for (int ch = beg; ch < end; ch += 4) {
        int p = ch + g;
        bool val = p < end;
        int idx = val ? g_i_src_u[p] : 0;
        uint4 v = g_lin_i[idx * 8 + c];
        acc8(a0, a1, a2, a3, v, val ? 1.0f : 0.0f);
    }
    xor_reduce_groups(a0, a1, a2, a3);
    float ss = a0.x*a0.x + a0.y*a0.y + a1.x*a1.x + a1.y*a1.y
             + a2.x*a2.x + a2.y*a2.y + a3.x*a3.x + a3.y*a3.y;
    #pragma unroll
    for (int o = 1; o <= 4; o <<= 1) ss += __shfl_xor_sync(0xffffffffu, ss, o);
    if (lane == 0) g_inv_i[r] = 1.0f / fmaxf(sqrtf(ss), EPS);
    if (g == 0) {
        g_emb_i0[r * 8 + c] = pack8(a0, a1, a2, a3);
        float4* o = (float4*)(out + (size_t)(N_USERS + r) * D + c * 8);
        o[0] = make_float4(a0.x, a0.y, a1.x, a1.y);
        o[1] = make_float4(a2.x, a2.y, a3.x, a3.y);
    }
}

// ---- weights + u-norm + FUSED layer-1 user propagation + pk_u packing (warp per user) ----
__global__ void __launch_bounds__(256) k_weights(const int* __restrict__ i_idx,
                                                 float* __restrict__ out) {
    int u = (blockIdx.x * blockDim.x + threadIdx.x) >> 5;
    if (u >= N_USERS) return;
    int lane = threadIdx.x & 31, g = lane >> 3, c = lane & 7;
    int beg = g_u_ptr[u], end = g_u_ptr[u + 1];
    uint4 av = g_emb_u0[u * 8 + c];
    float2 A0 = __half22float2(*(__half2*)&av.x);
    float2 A1 = __half22float2(*(__half2*)&av.y);
    float2 A2 = __half22float2(*(__half2*)&av.z);
    float2 A3 = __half22float2(*(__half2*)&av.w);
    float invu = g_inv_u[u];
    float sum = 0.f;
    for (int ch = beg; ch < end; ch += 4) {
        int e = ch + g;
        bool val = e < end;
        int i = val ? i_idx[e] : 0;
        uint4 bv = g_emb_i0[i * 8 + c];
        float2 b;
        float d = 0.f;
        b = __half22float2(*(__half2*)&bv.x); d = fmaf(A0.x, b.x, d); d = fmaf(A0.y, b.y, d);
        b = __half22float2(*(__half2*)&bv.y); d = fmaf(A1.x, b.x, d); d = fmaf(A1.y, b.y, d);
        b = __half22float2(*(__half2*)&bv.z); d = fmaf(A2.x, b.x, d); d = fmaf(A2.y, b.y, d);
        b = __half22float2(*(__half2*)&bv.w); d = fmaf(A3.x, b.x, d); d = fmaf(A3.y, b.y, d);
        #pragma unroll
        for (int o = 1; o <= 4; o <<= 1) d += __shfl_xor_sync(0xffffffffu, d, o);
        if (c == 0 && val) {
            float s = d * invu * g_inv_i[i];
            float w = fmaf(s, 0.5f, 0.5f);
            g_w_u[e] = w; g_w_i[g_slot[e]] = w; sum += w;
        }
    }
    sum += __shfl_xor_sync(0xffffffffu, sum, 8);
    sum += __shfl_xor_sync(0xffffffffu, sum, 16);
    float invd = 1.0f / (sum + 1e-7f);
    invd = __shfl_sync(0xffffffffu, invd, 0);
    __syncwarp();
    __threadfence_block();
    float2 a0 = {0,0}, a1 = {0,0}, a2 = {0,0}, a3 = {0,0};
    for (int ch = beg; ch < end; ch += 4) {
        int e = ch + g;
        bool val = e < end;
        int i = val ? i_idx[e] : 0;
        float wn = val ? g_w_u[e] * invd : 0.0f;
        if (c == 0 && val) g_pk_u[e] = make_int2(i, __float_as_int(wn));
        uint4 v = g_emb_i0[i * 8 + c];
        acc8(a0, a1, a2, a3, v, wn);
    }
    xor_reduce_groups(a0, a1, a2, a3);
    if (g == 0) {
        g_emb_u1[u * 8 + c] = pack8(a0, a1, a2, a3);
        store_out(out, u, c, a0, a1, a2, a3, 1.0f);
    }
}

// ---- i-norm + FUSED layer-1 item propagation + pk_i packing (warp per item) ----
__global__ void __launch_bounds__(256) k_norm_i(float* __restrict__ out) {
    int i = (blockIdx.x * blockDim.x + threadIdx.x) >> 5;
    if (i >= N_ITEMS) return;
    int lane = threadIdx.x & 31, g = lane >> 3, c = lane & 7;
    int beg = g_i_ptr[i], end = g_i_ptr[i + 1];
    float s = 0.f;
    for (int p = beg + lane; p < end; p += 32) s += g_w_i[p];
    #pragma unroll
    for (int o = 16; o; o >>= 1) s += __shfl_xor_sync(0xffffffffu, s, o);
    float invd = 1.0f / (s + 1e-7f);
    float2 a0 = {0,0}, a1 = {0,0}, a2 = {0,0}, a3 = {0,0};
    for (int ch = beg; ch < end; ch += 4) {
        int p = ch + g;
        bool val = p < end;
        int uu = val ? g_i_src_u[p] : 0;
        float wn = val ? g_w_i[p] * invd : 0.0f;
        if (c == 0 && val) g_pk_i[p] = make_int2(uu, __float_as_int(wn));
        uint4 v = g_emb_u0[uu * 8 + c];
        acc8(a0, a1, a2, a3, v, wn);
    }
    xor_reduce_groups(a0, a1, a2, a3);
    if (g == 0) {
        g_emb_i1[i * 8 + c] = pack8(a0, a1, a2, a3);
        store_out(out, N_USERS + i, c, a0, a1, a2, a3, 1.0f);
    }
}

// ---------------- propagation layers 2,3 ----------------
__global__ void __launch_bounds__(256) k_prop(float* __restrict__ out, int flip,
                                              float scale, int write_dst) {
    int r = (blockIdx.x * blockDim.x + threadIdx.x) >> 5;
    if (r >= N_TOTAL) return;
    int lane = threadIdx.x & 31, g = lane >> 3, c = lane & 7;
    const int2* __restrict__ pk;
    const uint4* __restrict__ src;
    uint4* __restrict__ dst;
    int beg, end, row;
    if (r < N_USERS) {
        row = r; pk = g_pk_u;
        src = flip ? g_emb_i1 : g_emb_i0;
        dst = flip ? g_emb_u0 : g_emb_u1;
        beg = g_u_ptr[r]; end = g_u_ptr[r + 1];
    } else {
        row = r - N_USERS; pk = g_pk_i;
        src = flip ? g_emb_u1 : g_emb_u0;
        dst = flip ? g_emb_i0 : g_emb_i1;
        beg = g_i_ptr[row]; end = g_i_ptr[row + 1];
    }
    float2 a0 = {0,0}, a1 = {0,0}, a2 = {0,0}, a3 = {0,0};
    for (int ch = beg; ch < end; ch += 4) {
        int e = ch + g;
        int2 p = (e < end) ? pk[e] : make_int2(0, 0);
        uint4 v = src[p.x * 8 + c];
        acc8(a0, a1, a2, a3, v, __int_as_float(p.y));
    }
    xor_reduce_groups(a0, a1, a2, a3);
    if (g == 0) {
        if (write_dst) dst[row * 8 + c] = pack8(a0, a1, a2, a3);
        store_out(out, r, c, a0, a1, a2, a3, scale);
    }
}

// ---------------- launch ----------------
extern "C" void kernel_launch(void* const* d_in, const int* in_sizes, int n_in,
                              void* d_out, int out_size) {
    const float* user_linear = (const float*)d_in[0];
    const float* item_linear = (const float*)d_in[1];
    const int*   u_idx       = (const int*)d_in[2];
    const int*   i_idx       = (const int*)d_in[3];
    float* out = (float*)d_out;

    int setup_threads = (N_USERS + N_ITEMS) * 8;
    k_setup<<<(setup_threads + 255) / 256, 256>>>(u_idx, user_linear, item_linear);
    // fused: item-degree counting (capturing ranks) + user-side base embeddings
    k_count_embu<<<NB_COUNT + NB_EMBU, 256>>>(i_idx, out);
    k_scan1<<<1, 1024>>>();
    k_scatter<<<(NNZ + 255) / 256, 256>>>(u_idx, i_idx);   // atomic-free
    k_emb_i<<<(N_ITEMS * 32 + 255) / 256, 256>>>(out);

    k_weights<<<(N_USERS * 32 + 255) / 256, 256>>>(i_idx, out);
    k_norm_i<<<(N_ITEMS * 32 + 255) / 256, 256>>>(out);

    k_prop<<<(N_TOTAL * 32 + 255) / 256, 256>>>(out, 1, 1.0f, 1);
    k_prop<<<(N_TOTAL * 32 + 255) / 256, 256>>>(out, 0, 0.25f, 0);
}

// round 9
// speedup vs baseline: 1.1330x; 1.0095x over previous
#include <cuda_runtime.h>
#include <cuda_fp16.h>

#define N_USERS 40000
#define N_ITEMS 20000
#define NNZ     1000000
#define D       64
#define N_TOTAL (N_USERS + N_ITEMS)
#define EPS     1e-8f
#define NB_COUNT ((NNZ + 255) / 256)
#define NB_EMBU  ((N_USERS * 32 + 255) / 256)
#define FULL 0xffffffffu

// ---------------- device scratch ----------------
__device__ uint4 g_lin_u[N_ITEMS * 8];
__device__ uint4 g_lin_i[N_USERS * 8];
__device__ uint4 g_emb_u0[N_USERS * 8];
__device__ uint4 g_emb_u1[N_USERS * 8];
__device__ uint4 g_emb_i0[N_ITEMS * 8];
__device__ uint4 g_emb_i1[N_ITEMS * 8];
__device__ float g_inv_u[N_USERS];
__device__ float g_inv_i[N_ITEMS];
__device__ float g_w_u[NNZ];
__device__ float g_w_i[NNZ];
__device__ int2  g_pk_u[NNZ];
__device__ int2  g_pk_i[NNZ];
__device__ int   g_i_src_u[NNZ];
__device__ int   g_slot[NNZ];     // phase 1: rank within item segment; phase 2: final slot
__device__ int   g_u_ptr[N_USERS + 1];
__device__ int   g_i_ptr[N_ITEMS + 1];
__device__ int   g_i_cnt[N_ITEMS];

// ---------------- helpers ----------------
__device__ __forceinline__ void acc8(float2& a0, float2& a1, float2& a2, float2& a3,
                                     uint4 v, float w) {
    float2 b;
    b = __half22float2(*(__half2*)&v.x); a0.x = fmaf(w, b.x, a0.x); a0.y = fmaf(w, b.y, a0.y);
    b = __half22float2(*(__half2*)&v.y); a1.x = fmaf(w, b.x, a1.x); a1.y = fmaf(w, b.y, a1.y);
    b = __half22float2(*(__half2*)&v.z); a2.x = fmaf(w, b.x, a2.x); a2.y = fmaf(w, b.y, a2.y);
    b = __half22float2(*(__half2*)&v.w); a3.x = fmaf(w, b.x, a3.x); a3.y = fmaf(w, b.y, a3.y);
}
__device__ __forceinline__ uint4 pack8(float2 a0, float2 a1, float2 a2, float2 a3) {
    uint4 r;
    *(__half2*)&r.x = __floats2half2_rn(a0.x, a0.y);
    *(__half2*)&r.y = __floats2half2_rn(a1.x, a1.y);
    *(__half2*)&r.z = __floats2half2_rn(a2.x, a2.y);
    *(__half2*)&r.w = __floats2half2_rn(a3.x, a3.y);
    return r;
}
__device__ __forceinline__ void xor_reduce_groups(float2& a0, float2& a1, float2& a2, float2& a3) {
    #pragma unroll
    for (int o = 8; o <= 16; o <<= 1) {
        a0.x += __shfl_xor_sync(FULL, a0.x, o);
        a0.y += __shfl_xor_sync(FULL, a0.y, o);
        a1.x += __shfl_xor_sync(FULL, a1.x, o);
        a1.y += __shfl_xor_sync(FULL, a1.y, o);
        a2.x += __shfl_xor_sync(FULL, a2.x, o);
        a2.y += __shfl_xor_sync(FULL, a2.y, o);
        a3.x += __shfl_xor_sync(FULL, a3.x, o);
        a3.y += __shfl_xor_sync(FULL, a3.y, o);
    }
}
__device__ __forceinline__ void store_out(float* __restrict__ out, int r, int c,
                                          float2 a0, float2 a1, float2 a2, float2 a3,
                                          float scale) {
    float4* o = (float4*)(out + (size_t)r * D + c * 8);
    float4 o0 = o[0], o1 = o[1];
    o0.x = (o0.x + a0.x) * scale; o0.y = (o0.y + a0.y) * scale;
    o0.z = (o0.z + a1.x) * scale; o0.w = (o0.w + a1.y) * scale;
    o1.x = (o1.x + a2.x) * scale; o1.y = (o1.y + a2.y) * scale;
    o1.z = (o1.z + a3.x) * scale; o1.w = (o1.w + a3.y) * scale;
    o[0] = o0; o[1] = o1;
}

// batched gather-accumulate: warp loads 32 idx once, then shuffles them out.
// Returns sum of rows (unit weight). All-lane uniform control flow.
__device__ __forceinline__ void gather_sum(const int* __restrict__ idxarr,
                                           const uint4* __restrict__ btab,
                                           int beg, int end, int lane, int g, int c,
                                           float2& a0, float2& a1, float2& a2, float2& a3) {
    for (int bs = beg; bs < end; bs += 32) {
        int n = end - bs; if (n > 32) n = 32;
        int myidx = (lane < n) ? idxarr[bs + lane] : 0;
        for (int kk = 0; kk < n; kk += 4) {
            int k = kk + g;
            bool valid = k < n;
            int idx = __shfl_sync(FULL, myidx, k & 31);
            uint4 v = btab[idx * 8 + c];
            acc8(a0, a1, a2, a3, v, valid ? 1.0f : 0.0f);
        }
    }
}

// ---------------- K1: zero counts + user CSR ptr + fp16 conversion ----------------
__global__ void k_setup(const int* __restrict__ u_idx,
                        const float* __restrict__ user_linear,
                        const float* __restrict__ item_linear) {
    int t = blockIdx.x * blockDim.x + threadIdx.x;
    if (t < N_ITEMS) g_i_cnt[t] = 0;
    if (t <= N_USERS) {
        int lo = 0, hi = NNZ;
        while (lo < hi) { int mid = (lo + hi) >> 1; if (u_idx[mid] < t) lo = mid + 1; else hi = mid; }
        g_u_ptr[t] = lo;
    }
    const int NU = N_ITEMS * 8;
    const int NI = N_USERS * 8;
    if (t < NU) {
        const float4* s = (const float4*)user_linear;
        float4 x0 = s[2 * t], x1 = s[2 * t + 1];
        g_lin_u[t] = pack8(make_float2(x0.x, x0.y), make_float2(x0.z, x0.w),
                           make_float2(x1.x, x1.y), make_float2(x1.z, x1.w));
    } else if (t < NU + NI) {
        int k = t - NU;
        const float4* s = (const float4*)item_linear;
        float4 x0 = s[2 * k], x1 = s[2 * k + 1];
        g_lin_i[k] = pack8(make_float2(x0.x, x0.y), make_float2(x0.z, x0.w),
                           make_float2(x1.x, x1.y), make_float2(x1.z, x1.w));
    }
}

// ---- K2: fused item-degree count (capturing ranks) + user-side base embeddings ----
__global__ void __launch_bounds__(256) k_count_embu(const int* __restrict__ i_idx,
                                                    float* __restrict__ out) {
    if (blockIdx.x < NB_COUNT) {
        int e = blockIdx.x * 256 + threadIdx.x;
        if (e < NNZ) g_slot[e] = atomicAdd(&g_i_cnt[i_idx[e]], 1);  // rank in segment
        return;
    }
    int r = ((blockIdx.x - NB_COUNT) * 256 + threadIdx.x) >> 5;
    if (r >= N_USERS) return;
    int lane = threadIdx.x & 31, g = lane >> 3, c = lane & 7;
    int beg = g_u_ptr[r], end = g_u_ptr[r + 1];
    float2 a0 = {0,0}, a1 = {0,0}, a2 = {0,0}, a3 = {0,0};
    gather_sum(i_idx, g_lin_u, beg, end, lane, g, c, a0, a1, a2, a3);
    xor_reduce_groups(a0, a1, a2, a3);
    float ss = a0.x*a0.x + a0.y*a0.y + a1.x*a1.x + a1.y*a1.y
             + a2.x*a2.x + a2.y*a2.y + a3.x*a3.x + a3.y*a3.y;
    #pragma unroll
    for (int o = 1; o <= 4; o <<= 1) ss += __shfl_xor_sync(FULL, ss, o);
    if (lane == 0) g_inv_u[r] = 1.0f / fmaxf(sqrtf(ss), EPS);
    if (g == 0) {
        g_emb_u0[r * 8 + c] = pack8(a0, a1, a2, a3);
        float4* o = (float4*)(out + (size_t)r * D + c * 8);
        o[0] = make_float4(a0.x, a0.y, a1.x, a1.y);
        o[1] = make_float4(a2.x, a2.y, a3.x, a3.y);
    }
}

// ---------------- K3: single-block vectorized exclusive scan ----------------
__global__ void __launch_bounds__(1024) k_scan1() {
    __shared__ int wsum[32];
    int tid = threadIdx.x, lane = tid & 31, wid = tid >> 5;
    const int4* cnt4 = (const int4*)g_i_cnt;
    int4* ptr4 = (int4*)g_i_ptr;
    int v[20];
    int s = 0;
    if (tid < 1000) {
        #pragma unroll
        for (int k = 0; k < 5; ++k) {
            int4 x = cnt4[tid * 5 + k];
            v[4*k+0] = s; s += x.x;
            v[4*k+1] = s; s += x.y;
            v[4*k+2] = s; s += x.z;
            v[4*k+3] = s; s += x.w;
        }
    }
    int t = s;
    #pragma unroll
    for (int o = 1; o < 32; o <<= 1) { int y = __shfl_up_sync(FULL, t, o); if (lane >= o) t += y; }
    if (lane == 31) wsum[wid] = t;
    __syncthreads();
    if (wid == 0) {
        int x = wsum[lane];
        #pragma unroll
        for (int o = 1; o < 32; o <<= 1) { int y = __shfl_up_sync(FULL, x, o); if (lane >= o) x += y; }
        wsum[lane] = x;
    }
    __syncthreads();
    int offset = (t - s) + (wid ? wsum[wid - 1] : 0);
    if (tid < 1000) {
        #pragma unroll
        for (int k = 0; k < 5; ++k) {
            ptr4[tid * 5 + k] = make_int4(offset + v[4*k], offset + v[4*k+1],
                                          offset + v[4*k+2], offset + v[4*k+3]);
        }
    }
    if (tid == 0) g_i_ptr[N_ITEMS] = NNZ;
}

// ---------------- K4: atomic-free scatter using precomputed ranks ----------------
__global__ void k_scatter(const int* __restrict__ u_idx, const int* __restrict__ i_idx) {
    int e = blockIdx.x * blockDim.x + threadIdx.x;
    if (e >= NNZ) return;
    int i = i_idx[e];
    int pos = g_i_ptr[i] + g_slot[e];
    g_i_src_u[pos] = u_idx[e];
    g_slot[e] = pos;
}

// ---------------- item-side base embeddings ----------------
__global__ void __launch_bounds__(256) k_emb_i(float* __restrict__ out) {
    int r = (blockIdx.x * blockDim.x + threadIdx.x) >> 5;
    if (r >= N_ITEMS) return;
    int lane = threadIdx.x & 31, g = lane >> 3, c = lane & 7;
    int beg = g_i_ptr[r], end = g_i_ptr[r + 1];
    float2 a0 = {0,0}, a1 = {0,0}, a2 = {0,0}, a3 = {0,0};
    gather_sum(g_i_src_u, g_lin_i, beg, end, lane, g, c, a0, a1, a2, a3);
    xor_reduce_groups(a0, a1, a2, a3);
    float ss = a0.x*a0.x + a0.y*a0.y + a1.x*a1.x + a1.y*a1.y
             + a2.x*a2.x + a2.y*a2.y + a3.x*a3.x + a3.y*a3.y;
    #pragma unroll
    for (int o = 1; o <= 4; o <<= 1) ss += __shfl_xor_sync(FULL, ss, o);
    if (lane == 0) g_inv_i[r] = 1.0f / fmaxf(sqrtf(ss), EPS);
    if (g == 0) {
        g_emb_i0[r * 8 + c] = pack8(a0, a1, a2, a3);
        float4* o = (float4*)(out + (size_t)(N_USERS + r) * D + c * 8);
        o[0] = make_float4(a0.x, a0.y, a1.x, a1.y);
        o[1] = make_float4(a2.x, a2.y, a3.x, a3.y);
    }
}

// ---- weights + u-norm + FUSED layer-1 user propagation + pk_u packing (warp per user) ----
__global__ void __launch_bounds__(256) k_weights(const int* __restrict__ i_idx,
                                                 float* __restrict__ out) {
    int u = (blockIdx.x * blockDim.x + threadIdx.x) >> 5;
    if (u >= N_USERS) return;
    int lane = threadIdx.x & 31, g = lane >> 3, c = lane & 7;
    int beg = g_u_ptr[u], end = g_u_ptr[u + 1];
    uint4 av = g_emb_u0[u * 8 + c];
    float2 A0 = __half22float2(*(__half2*)&av.x);
    float2 A1 = __half22float2(*(__half2*)&av.y);
    float2 A2 = __half22float2(*(__half2*)&av.z);
    float2 A3 = __half22float2(*(__half2*)&av.w);
    float invu = g_inv_u[u];
    float sum = 0.f;
    // pass 1: cosine weights (batched idx)
    for (int bs = beg; bs < end; bs += 32) {
        int n = end - bs; if (n > 32) n = 32;
        int myidx = (lane < n) ? i_idx[bs + lane] : 0;
        for (int kk = 0; kk < n; kk += 4) {
            int k = kk + g;
            bool valid = k < n;
            int i = __shfl_sync(FULL, myidx, k & 31);
            uint4 bv = g_emb_i0[i * 8 + c];
            float2 b;
            float d = 0.f;
            b = __half22float2(*(__half2*)&bv.x); d = fmaf(A0.x, b.x, d); d = fmaf(A0.y, b.y, d);
            b = __half22float2(*(__half2*)&bv.y); d = fmaf(A1.x, b.x, d); d = fmaf(A1.y, b.y, d);
            b = __half22float2(*(__half2*)&bv.z); d = fmaf(A2.x, b.x, d); d = fmaf(A2.y, b.y, d);
            b = __half22float2(*(__half2*)&bv.w); d = fmaf(A3.x, b.x, d); d = fmaf(A3.y, b.y, d);
            #pragma unroll
            for (int o = 1; o <= 4; o <<= 1) d += __shfl_xor_sync(FULL, d, o);
            if (c == 0 && valid) {
                int e = bs + k;
                float s = d * invu * g_inv_i[i];
                float w = fmaf(s, 0.5f, 0.5f);
                g_w_u[e] = w; g_w_i[g_slot[e]] = w; sum += w;
            }
        }
    }
    sum += __shfl_xor_sync(FULL, sum, 8);
    sum += __shfl_xor_sync(FULL, sum, 16);
    float invd = 1.0f / (sum + 1e-7f);
    invd = __shfl_sync(FULL, invd, 0);
    __syncwarp();
    __threadfence_block();
    // pass 2: layer-1 user propagation + pk_u packing (batched idx+w)
    float2 a0 = {0,0}, a1 = {0,0}, a2 = {0,0}, a3 = {0,0};
    for (int bs = beg; bs < end; bs += 32) {
        int n = end - bs; if (n > 32) n = 32;
        int myidx = (lane < n) ? i_idx[bs + lane] : 0;
        float myw = (lane < n) ? g_w_u[bs + lane] * invd : 0.0f;
        if (lane < n) g_pk_u[bs + lane] = make_int2(myidx, __float_as_int(myw));
        for (int kk = 0; kk < n; kk += 4) {
            int k = kk + g;
            bool valid = k < n;
            int i = __shfl_sync(FULL, myidx, k & 31);
            float wn = __shfl_sync(FULL, myw, k & 31);
            uint4 v = g_emb_i0[i * 8 + c];
            acc8(a0, a1, a2, a3, v, valid ? wn : 0.0f);
        }
    }
    xor_reduce_groups(a0, a1, a2, a3);
    if (g == 0) {
        g_emb_u1[u * 8 + c] = pack8(a0, a1, a2, a3);
        store_out(out, u, c, a0, a1, a2, a3, 1.0f);
    }
}

// ---- i-norm + FUSED layer-1 item propagation + pk_i packing (warp per item) ----
__global__ void __launch_bounds__(256) k_norm_i(float* __restrict__ out) {
    int i = (blockIdx.x * blockDim.x + threadIdx.x) >> 5;
    if (i >= N_ITEMS) return;
    int lane = threadIdx.x & 31, g = lane >> 3, c = lane & 7;
    int beg = g_i_ptr[i], end = g_i_ptr[i + 1];
    float s = 0.f;
    for (int p = beg + lane; p < end; p += 32) s += g_w_i[p];
    #pragma unroll
    for (int o = 16; o; o >>= 1) s += __shfl_xor_sync(FULL, s, o);
    float invd = 1.0f / (s + 1e-7f);
    float2 a0 = {0,0}, a1 = {0,0}, a2 = {0,0}, a3 = {0,0};
    for (int bs = beg; bs < end; bs += 32) {
        int n = end - bs; if (n > 32) n = 32;
        int myidx = (lane < n) ? g_i_src_u[bs + lane] : 0;
        float myw = (lane < n) ? g_w_i[bs + lane] * invd : 0.0f;
        if (lane < n) g_pk_i[bs + lane] = make_int2(myidx, __float_as_int(myw));
        for (int kk = 0; kk < n; kk += 4) {
            int k = kk + g;
            bool valid = k < n;
            int uu = __shfl_sync(FULL, myidx, k & 31);
            float wn = __shfl_sync(FULL, myw, k & 31);
            uint4 v = g_emb_u0[uu * 8 + c];
            acc8(a0, a1, a2, a3, v, valid ? wn : 0.0f);
        }
    }
    xor_reduce_groups(a0, a1, a2, a3);
    if (g == 0) {
        g_emb_i1[i * 8 + c] = pack8(a0, a1, a2, a3);
        store_out(out, N_USERS + i, c, a0, a1, a2, a3, 1.0f);
    }
}

// ---------------- propagation layers 2,3 ----------------
__global__ void __launch_bounds__(256) k_prop(float* __restrict__ out, int flip,
                                              float scale, int write_dst) {
    int r = (blockIdx.x * blockDim.x + threadIdx.x) >> 5;
    if (r >= N_TOTAL) return;
    int lane = threadIdx.x & 31, g = lane >> 3, c = lane & 7;
    const int2* __restrict__ pk;
    const uint4* __restrict__ src;
    uint4* __restrict__ dst;
    int beg, end, row;
    if (r < N_USERS) {
        row = r; pk = g_pk_u;
        src = flip ? g_emb_i1 : g_emb_i0;
        dst = flip ? g_emb_u0 : g_emb_u1;
        beg = g_u_ptr[r]; end = g_u_ptr[r + 1];
    } else {
        row = r - N_USERS; pk = g_pk_i;
        src = flip ? g_emb_u1 : g_emb_u0;
        dst = flip ? g_emb_i0 : g_emb_i1;
        beg = g_i_ptr[row]; end = g_i_ptr[row + 1];
    }
    float2 a0 = {0,0}, a1 = {0,0}, a2 = {0,0}, a3 = {0,0};
    for (int bs = beg; bs < end; bs += 32) {
        int n = end - bs; if (n > 32) n = 32;
        int2 myp = (lane < n) ? pk[bs + lane] : make_int2(0, 0);
        for (int kk = 0; kk < n; kk += 4) {
            int k = kk + g;
            bool valid = k < n;
            int idx = __shfl_sync(FULL, myp.x, k & 31);
            float wn = __int_as_float(__shfl_sync(FULL, myp.y, k & 31));
            uint4 v = src[idx * 8 + c];
            acc8(a0, a1, a2, a3, v, valid ? wn : 0.0f);
        }
    }
    xor_reduce_groups(a0, a1, a2, a3);
    if (g == 0) {
        if (write_dst) dst[row * 8 + c] = pack8(a0, a1, a2, a3);
        store_out(out, r, c, a0, a1, a2, a3, scale);
    }
}

// ---------------- launch ----------------
extern "C" void kernel_launch(void* const* d_in, const int* in_sizes, int n_in,
                              void* d_out, int out_size) {
    const float* user_linear = (const float*)d_in[0];
    const float* item_linear = (const float*)d_in[1];
    const int*   u_idx       = (const int*)d_in[2];
    const int*   i_idx       = (const int*)d_in[3];
    float* out = (float*)d_out;

    int setup_threads = (N_USERS + N_ITEMS) * 8;
    k_setup<<<(setup_threads + 255) / 256, 256>>>(u_idx, user_linear, item_linear);
    k_count_embu<<<NB_COUNT + NB_EMBU, 256>>>(i_idx, out);
    k_scan1<<<1, 1024>>>();
    k_scatter<<<(NNZ + 255) / 256, 256>>>(u_idx, i_idx);
    k_emb_i<<<(N_ITEMS * 32 + 255) / 256, 256>>>(out);

    k_weights<<<(N_USERS * 32 + 255) / 256, 256>>>(i_idx, out);
    k_norm_i<<<(N_ITEMS * 32 + 255) / 256, 256>>>(out);

    k_prop<<<(N_TOTAL * 32 + 255) / 256, 256>>>(out, 1, 1.0f, 1);
    k_prop<<<(N_TOTAL * 32 + 255) / 256, 256>>>(out, 0, 0.25f, 0);
}